// round 6
// baseline (speedup 1.0000x reference)
#include <cuda_runtime.h>
#include <cstdint>

#define MAXN 50000
#define MAXE 1600000
#define D 64

// ---- scratch (__device__ globals; no allocations allowed) ----
__device__ int   g_cnt[MAXN];        // per-src degree
__device__ int   g_pos[MAXN];        // placement cursor
__device__ int   g_rowstart[MAXN];   // exclusive prefix of g_cnt
__device__ int   g_edst[MAXE];       // dst sorted by src
__device__ float g_Sx[MAXN * 4];     // per-src scalar sums: Spos, Sneg, Sw, pad
__device__ float g_hmu[MAXN * D];    // relu(mu @ W3^T)
__device__ float g_v[3 * D];         // v1=W4a@relu(W1), v1n=W4a@relu(-W1), v2=W4b@relu(W2)

__device__ __forceinline__ float relu(float a) { return fmaxf(a, 0.f); }

__device__ __forceinline__ void red_add_v4(float* addr, float4 v) {
    asm volatile("red.global.add.v4.f32 [%0], {%1,%2,%3,%4};"
                 :: "l"(addr), "f"(v.x), "f"(v.y), "f"(v.z), "f"(v.w)
                 : "memory");
}

// K1: h_mu = relu(mu @ W3^T) (16 nodes/block, W3 transposed in smem)
//     + zero the counters/accumulators (grid-stride prologue).
__global__ __launch_bounds__(256) void k_hmu_zero(const float* __restrict__ mu,
                                                  const float* __restrict__ W3, int N) {
    int t = threadIdx.x;
    int gt = blockIdx.x * 256 + t;
    if (gt < N) {
        g_cnt[gt] = 0;
        g_pos[gt] = 0;
        ((float4*)g_Sx)[gt] = make_float4(0.f, 0.f, 0.f, 0.f);
    }

    __shared__ float  sW3t[64 * 64];   // [k][o]
    __shared__ float4 smu4[16 * 16];
    for (int i = t; i < 64 * 64; i += 256) {
        int o = i >> 6, k = i & 63;
        sW3t[k * 64 + o] = W3[i];
    }
    int base = blockIdx.x * 16;
    {
        int g = t >> 4, q = t & 15;
        int n = base + g;
        float4 m = make_float4(0.f, 0.f, 0.f, 0.f);
        if (n < N) m = ((const float4*)mu)[(size_t)n * 16 + q];
        smu4[g * 16 + q] = m;
    }
    __syncthreads();
    int g = t >> 4, o4 = t & 15;
    int n = base + g;
    const float* smu = (const float*)smu4;
    float4 acc = make_float4(0.f, 0.f, 0.f, 0.f);
#pragma unroll
    for (int k = 0; k < 64; k++) {
        float m = smu[g * 64 + k];
        float4 w = ((const float4*)sW3t)[k * 16 + o4];
        acc.x = fmaf(m, w.x, acc.x);
        acc.y = fmaf(m, w.y, acc.y);
        acc.z = fmaf(m, w.z, acc.z);
        acc.w = fmaf(m, w.w, acc.w);
    }
    if (n < N) {
        float4 r = make_float4(relu(acc.x), relu(acc.y), relu(acc.z), relu(acc.w));
        ((float4*)g_hmu)[(size_t)n * 16 + o4] = r;
    }
}

// K2: histogram of src
__global__ __launch_bounds__(256) void k_hist(const int* __restrict__ ei, int E) {
    int stride = gridDim.x * blockDim.x;
    for (int e = blockIdx.x * blockDim.x + threadIdx.x; e < E; e += stride)
        atomicAdd(&g_cnt[ei[e]], 1);
}

// K3: single-block exclusive scan of g_cnt -> g_rowstart, plus the three
//     rank-1 vectors (vprep) on threads 0..63.
__global__ __launch_bounds__(1024) void k_scan(const float* __restrict__ W1,
                                               const float* __restrict__ W2,
                                               const float* __restrict__ W4, int N) {
    __shared__ int spart[1024];
    int t = threadIdx.x;
    int chunk = (N + 1023) / 1024;
    int lo = t * chunk;
    int hi = min(lo + chunk, N);
    int sum = 0;
    for (int i = lo; i < hi; i++) sum += g_cnt[i];
    spart[t] = sum;
    __syncthreads();
#pragma unroll
    for (int off = 1; off < 1024; off <<= 1) {
        int add = (t >= off) ? spart[t - off] : 0;
        __syncthreads();
        spart[t] += add;
        __syncthreads();
    }
    int run = spart[t] - sum;   // exclusive prefix
    for (int i = lo; i < hi; i++) {
        g_rowstart[i] = run;
        run += g_cnt[i];
    }
    if (t < 64) {
        int o = t;
        float a = 0.f, b = 0.f, c = 0.f;
#pragma unroll 8
        for (int k = 0; k < 64; k++) {
            float w4a = W4[o * 192 + k];
            float w4b = W4[o * 192 + 64 + k];
            float w1 = W1[k], w2 = W2[k];
            a = fmaf(w4a, relu(w1), a);
            b = fmaf(w4a, relu(-w1), b);
            c = fmaf(w4b, relu(w2), c);
        }
        g_v[o] = a;
        g_v[64 + o] = b;
        g_v[128 + o] = c;
    }
}

// K4: place edges into CSR slots AND reduce the per-src scalar triple here.
__global__ __launch_bounds__(256) void k_place(const int* __restrict__ ei,
                                               const float* __restrict__ ew,
                                               const float* __restrict__ x, int E) {
    int stride = gridDim.x * blockDim.x;
    for (int e = blockIdx.x * blockDim.x + threadIdx.x; e < E; e += stride) {
        int src = ei[e];
        int dst = ei[(size_t)E + e];
        int slot = g_rowstart[src] + atomicAdd(&g_pos[src], 1);
        g_edst[slot] = dst;
        float w = ew[e];
        float xd = x[dst];
        red_add_v4(&g_Sx[(size_t)src * 4],
                   make_float4(relu(xd), relu(-xd), w, 0.f));
    }
}

// K5: fused gather-reduce + finalize. 16 nodes/block, 16 threads/node.
// Gather unrolled x4 for MLP; scalars come precomputed from g_Sx.
__global__ __launch_bounds__(256) void k_node(const float* __restrict__ x,
                                              const float* __restrict__ W1,
                                              const float* __restrict__ W4,
                                              float* __restrict__ out, int N) {
    __shared__ float  sW4t[64 * 64];   // [k][o] of W4 cols 128..191
    __shared__ float4 sAgg4[16 * 16];
    __shared__ float  sv[192];
    __shared__ float  sW1[64];
    int t = threadIdx.x;
    for (int i = t; i < 64 * 64; i += 256) {
        int o = i >> 6, k = i & 63;
        sW4t[k * 64 + o] = W4[o * 192 + 128 + k];
    }
    if (t < 192) sv[t] = g_v[t];
    if (t < 64)  sW1[t] = W1[t];

    int g = t >> 4, j = t & 15;
    int n = blockIdx.x * 16 + g;

    float4 acc = make_float4(0.f, 0.f, 0.f, 0.f);
    if (n < N) {
        int deg = g_cnt[n];
        const int* ed = g_edst + g_rowstart[n];
        const float4* hmu4 = (const float4*)g_hmu;
        int i = 0;
        for (; i + 4 <= deg; i += 4) {
            int d0 = ed[i], d1 = ed[i + 1], d2 = ed[i + 2], d3 = ed[i + 3];
            float4 v0 = hmu4[(size_t)d0 * 16 + j];
            float4 v1 = hmu4[(size_t)d1 * 16 + j];
            float4 v2 = hmu4[(size_t)d2 * 16 + j];
            float4 v3 = hmu4[(size_t)d3 * 16 + j];
            acc.x += (v0.x + v1.x) + (v2.x + v3.x);
            acc.y += (v0.y + v1.y) + (v2.y + v3.y);
            acc.z += (v0.z + v1.z) + (v2.z + v3.z);
            acc.w += (v0.w + v1.w) + (v2.w + v3.w);
        }
        for (; i < deg; i++) {
            float4 v = hmu4[(size_t)ed[i] * 16 + j];
            acc.x += v.x; acc.y += v.y; acc.z += v.z; acc.w += v.w;
        }
    }
    sAgg4[g * 16 + j] = acc;
    __syncthreads();

    // Phase B: thread computes outputs o0..o0+3 of node n
    int o4 = j;
    int o0 = o4 * 4;
    if (n >= N) return;
    float4 sx = ((const float4*)g_Sx)[n];   // broadcast within group
    const float* sAgg = (const float*)sAgg4;
    float4 z;
    z.x = sx.x * sv[o0 + 0] + sx.y * sv[64 + o0 + 0] + sx.z * sv[128 + o0 + 0];
    z.y = sx.x * sv[o0 + 1] + sx.y * sv[64 + o0 + 1] + sx.z * sv[128 + o0 + 1];
    z.z = sx.x * sv[o0 + 2] + sx.y * sv[64 + o0 + 2] + sx.z * sv[128 + o0 + 2];
    z.w = sx.x * sv[o0 + 3] + sx.y * sv[64 + o0 + 3] + sx.z * sv[128 + o0 + 3];
#pragma unroll
    for (int k = 0; k < 64; k++) {
        float a = sAgg[g * 64 + k];
        float4 w = ((const float4*)sW4t)[k * 16 + o4];
        z.x = fmaf(a, w.x, z.x);
        z.y = fmaf(a, w.y, z.y);
        z.z = fmaf(a, w.z, z.z);
        z.w = fmaf(a, w.w, z.w);
    }
    float xn = x[n];
    float4 hm = ((const float4*)g_hmu)[(size_t)n * 16 + o4];
    float4 r;
    r.x = relu(relu(xn * sW1[o0 + 0]) + hm.x + relu(z.x));
    r.y = relu(relu(xn * sW1[o0 + 1]) + hm.y + relu(z.y));
    r.z = relu(relu(xn * sW1[o0 + 2]) + hm.z + relu(z.z));
    r.w = relu(relu(xn * sW1[o0 + 3]) + hm.w + relu(z.w));
    ((float4*)out)[(size_t)n * 16 + o4] = r;
}

extern "C" void kernel_launch(void* const* d_in, const int* in_sizes, int n_in,
                              void* d_out, int out_size) {
    const float* mu  = (const float*)d_in[0];
    const float* x   = (const float*)d_in[1];
    const int*   ei  = (const int*)d_in[2];     // int32 (JAX x64 disabled)
    const float* ew  = (const float*)d_in[3];
    const float* W1  = (const float*)d_in[4];
    const float* W2  = (const float*)d_in[5];
    const float* W3  = (const float*)d_in[6];
    const float* W4  = (const float*)d_in[7];
    float* out = (float*)d_out;

    int N = in_sizes[1];   // x: [N,1]
    int E = in_sizes[3];   // edge_w: [E]

    k_hmu_zero<<<(N + 15) / 16, 256>>>(mu, W3, N);
    k_hist<<<(E + 255) / 256, 256>>>(ei, E);
    k_scan<<<1, 1024>>>(W1, W2, W4, N);
    k_place<<<(E + 255) / 256, 256>>>(ei, ew, x, E);
    k_node<<<(N + 15) / 16, 256>>>(x, W1, W4, out, N);
}

// round 7
// speedup vs baseline: 1.1581x; 1.1581x over previous
#include <cuda_runtime.h>
#include <cstdint>

#define MAXN 50000
#define MAXE 1600000
#define D 64

// ---- scratch (__device__ globals; no allocations allowed) ----
__device__ float g_agg[MAXN * D];    // segment-sum of h_mu[dst] over src
__device__ float g_Sx[MAXN * 4];     // per-src scalar sums: Spos, Sneg, Sw, pad
__device__ float g_hmu[MAXN * D];    // relu(mu @ W3^T)
__device__ float g_v[3 * D];         // v1=W4a@relu(W1), v1n=W4a@relu(-W1), v2=W4b@relu(W2)

__device__ __forceinline__ float relu(float a) { return fmaxf(a, 0.f); }

__device__ __forceinline__ void red_add_v4(float* addr, float4 v) {
    asm volatile("red.global.add.v4.f32 [%0], {%1,%2,%3,%4};"
                 :: "l"(addr), "f"(v.x), "f"(v.y), "f"(v.z), "f"(v.w)
                 : "memory");
}

// K1: h_mu = relu(mu @ W3^T), 16 nodes/block, W3 transposed in smem.
//     Prologue zeroes g_agg/g_Sx; block 0 also computes the rank-1 vectors.
__global__ __launch_bounds__(256) void k_hmu_zero(const float* __restrict__ mu,
                                                  const float* __restrict__ W3,
                                                  const float* __restrict__ W1,
                                                  const float* __restrict__ W2,
                                                  const float* __restrict__ W4, int N) {
    int t = threadIdx.x;
    int gt = blockIdx.x * 256 + t;                  // grid has exactly N*16 threads
    float4 z4 = make_float4(0.f, 0.f, 0.f, 0.f);
    if (gt < N * 16) ((float4*)g_agg)[gt] = z4;     // N*16 float4s = N*64 floats
    if (gt < N)      ((float4*)g_Sx)[gt] = z4;

    __shared__ float  sW3t[64 * 64];   // [k][o]
    __shared__ float4 smu4[16 * 16];
    for (int i = t; i < 64 * 64; i += 256) {
        int o = i >> 6, k = i & 63;
        sW3t[k * 64 + o] = W3[i];
    }
    int base = blockIdx.x * 16;
    {
        int g = t >> 4, q = t & 15;
        int n = base + g;
        float4 m = make_float4(0.f, 0.f, 0.f, 0.f);
        if (n < N) m = ((const float4*)mu)[(size_t)n * 16 + q];
        smu4[g * 16 + q] = m;
    }
    __syncthreads();
    int g = t >> 4, o4 = t & 15;
    int n = base + g;
    const float* smu = (const float*)smu4;
    float4 acc = make_float4(0.f, 0.f, 0.f, 0.f);
#pragma unroll
    for (int k = 0; k < 64; k++) {
        float m = smu[g * 64 + k];
        float4 w = ((const float4*)sW3t)[k * 16 + o4];
        acc.x = fmaf(m, w.x, acc.x);
        acc.y = fmaf(m, w.y, acc.y);
        acc.z = fmaf(m, w.z, acc.z);
        acc.w = fmaf(m, w.w, acc.w);
    }
    if (n < N) {
        float4 r = make_float4(relu(acc.x), relu(acc.y), relu(acc.z), relu(acc.w));
        ((float4*)g_hmu)[(size_t)n * 16 + o4] = r;
    }

    // vprep: the three rank-1 vectors (block 0, threads 0..63)
    if (blockIdx.x == 0 && t < 64) {
        int o = t;
        float a = 0.f, b = 0.f, c = 0.f;
#pragma unroll 8
        for (int k = 0; k < 64; k++) {
            float w4a = W4[o * 192 + k];
            float w4b = W4[o * 192 + 64 + k];
            float w1 = W1[k], w2 = W2[k];
            a = fmaf(w4a, relu(w1), a);
            b = fmaf(w4a, relu(-w1), b);
            c = fmaf(w4b, relu(w2), c);
        }
        g_v[o] = a;
        g_v[64 + o] = b;
        g_v[128 + o] = c;
    }
}

// K2: scatter edge kernel. 16 threads per group; each group processes 4 edges.
// Each thread gathers 4 independent float4s of h_mu[dst] (MLP=4), then fires
// 4 red.global.add.v4 into agg[src]. Lane 0 also reduces the 3 scalars.
__global__ __launch_bounds__(256) void k_edge(const int* __restrict__ ei,
                                              const float* __restrict__ x,
                                              const float* __restrict__ ew, int E) {
    int gid = (blockIdx.x * 256 + threadIdx.x) >> 4;
    int j = threadIdx.x & 15;
    int e0 = gid * 4;
    if (e0 >= E) return;
    int ne = min(4, E - e0);

    int srcs[4], dsts[4];
#pragma unroll
    for (int q = 0; q < 4; q++) {
        if (q < ne) {
            srcs[q] = ei[e0 + q];
            dsts[q] = ei[(size_t)E + e0 + q];
        }
    }
    const float4* hmu4 = (const float4*)g_hmu;
    float4 v[4];
#pragma unroll
    for (int q = 0; q < 4; q++)
        if (q < ne) v[q] = hmu4[(size_t)dsts[q] * 16 + j];
#pragma unroll
    for (int q = 0; q < 4; q++)
        if (q < ne) red_add_v4(&g_agg[(size_t)srcs[q] * 64 + (size_t)j * 4], v[q]);

    if (j == 0) {
#pragma unroll
        for (int q = 0; q < 4; q++) {
            if (q < ne) {
                float xd = x[dsts[q]];
                red_add_v4(&g_Sx[(size_t)srcs[q] * 4],
                           make_float4(relu(xd), relu(-xd), ew[e0 + q], 0.f));
            }
        }
    }
}

// K3: finalize. 16 nodes/block. agg row -> smem; 64x64 GEMV vs W4c (transposed)
//     + rank-1 scalar terms + epilogue relu chain.
__global__ __launch_bounds__(256) void k_final(const float* __restrict__ x,
                                               const float* __restrict__ W1,
                                               const float* __restrict__ W4,
                                               float* __restrict__ out, int N) {
    __shared__ float  sW4t[64 * 64];   // [k][o] of W4 cols 128..191
    __shared__ float4 sAgg4[16 * 16];
    __shared__ float  sv[192];
    __shared__ float  sW1[64];
    int t = threadIdx.x;
    for (int i = t; i < 64 * 64; i += 256) {
        int o = i >> 6, k = i & 63;
        sW4t[k * 64 + o] = W4[o * 192 + 128 + k];
    }
    if (t < 192) sv[t] = g_v[t];
    if (t < 64)  sW1[t] = W1[t];

    int g = t >> 4, j = t & 15;
    int n = blockIdx.x * 16 + g;
    float4 a4 = make_float4(0.f, 0.f, 0.f, 0.f);
    if (n < N) a4 = ((const float4*)g_agg)[(size_t)n * 16 + j];
    sAgg4[g * 16 + j] = a4;
    __syncthreads();

    if (n >= N) return;
    int o4 = j;
    int o0 = o4 * 4;
    float4 sx = ((const float4*)g_Sx)[n];
    const float* sAgg = (const float*)sAgg4;
    float4 z;
    z.x = sx.x * sv[o0 + 0] + sx.y * sv[64 + o0 + 0] + sx.z * sv[128 + o0 + 0];
    z.y = sx.x * sv[o0 + 1] + sx.y * sv[64 + o0 + 1] + sx.z * sv[128 + o0 + 1];
    z.z = sx.x * sv[o0 + 2] + sx.y * sv[64 + o0 + 2] + sx.z * sv[128 + o0 + 2];
    z.w = sx.x * sv[o0 + 3] + sx.y * sv[64 + o0 + 3] + sx.z * sv[128 + o0 + 3];
#pragma unroll
    for (int k = 0; k < 64; k++) {
        float a = sAgg[g * 64 + k];
        float4 w = ((const float4*)sW4t)[k * 16 + o4];
        z.x = fmaf(a, w.x, z.x);
        z.y = fmaf(a, w.y, z.y);
        z.z = fmaf(a, w.z, z.z);
        z.w = fmaf(a, w.w, z.w);
    }
    float xn = x[n];
    float4 hm = ((const float4*)g_hmu)[(size_t)n * 16 + o4];
    float4 r;
    r.x = relu(relu(xn * sW1[o0 + 0]) + hm.x + relu(z.x));
    r.y = relu(relu(xn * sW1[o0 + 1]) + hm.y + relu(z.y));
    r.z = relu(relu(xn * sW1[o0 + 2]) + hm.z + relu(z.z));
    r.w = relu(relu(xn * sW1[o0 + 3]) + hm.w + relu(z.w));
    ((float4*)out)[(size_t)n * 16 + o4] = r;
}

extern "C" void kernel_launch(void* const* d_in, const int* in_sizes, int n_in,
                              void* d_out, int out_size) {
    const float* mu  = (const float*)d_in[0];
    const float* x   = (const float*)d_in[1];
    const int*   ei  = (const int*)d_in[2];     // int32 (JAX x64 disabled)
    const float* ew  = (const float*)d_in[3];
    const float* W1  = (const float*)d_in[4];
    const float* W2  = (const float*)d_in[5];
    const float* W3  = (const float*)d_in[6];
    const float* W4  = (const float*)d_in[7];
    float* out = (float*)d_out;

    int N = in_sizes[1];   // x: [N,1]
    int E = in_sizes[3];   // edge_w: [E]

    k_hmu_zero<<<(N + 15) / 16, 256>>>(mu, W3, W1, W2, W4, N);

    int ngroups = (E + 3) / 4;                       // 4 edges per 16-thread group
    int blocks = (ngroups * 16 + 255) / 256;
    k_edge<<<blocks, 256>>>(ei, x, ew, E);

    k_final<<<(N + 15) / 16, 256>>>(x, W1, W4, out, N);
}

// round 8
// speedup vs baseline: 1.8202x; 1.5717x over previous
#include <cuda_runtime.h>
#include <cstdint>

#define MAXN 50000
#define MAXE 1600000
#define D 64

// ---- scratch (__device__ globals; no allocations allowed) ----
__device__ float g_agg[MAXN * D];    // segment-sum of h_mu[dst] over src
__device__ float g_Sx[MAXN * 4];     // per-src scalar sums: Spos, Sneg, Sw, pad
__device__ float g_hmu[MAXN * D];    // relu(mu @ W3^T)
__device__ float g_v[3 * D];         // v1=W4a@relu(W1), v1n=W4a@relu(-W1), v2=W4b@relu(W2)

__device__ __forceinline__ float relu(float a) { return fmaxf(a, 0.f); }

__device__ __forceinline__ void red_add_v4(float* addr, float4 v) {
    asm volatile("red.global.add.v4.f32 [%0], {%1,%2,%3,%4};"
                 :: "l"(addr), "f"(v.x), "f"(v.y), "f"(v.z), "f"(v.w)
                 : "memory");
}

// K1: h_mu = relu(mu @ W3^T). 64 nodes/block, 4x4 register tile per thread.
//     Prologue zeroes g_agg/g_Sx; block 0 computes the rank-1 vectors.
__global__ __launch_bounds__(256) void k_hmu_zero(const float* __restrict__ mu,
                                                  const float* __restrict__ W3,
                                                  const float* __restrict__ W1,
                                                  const float* __restrict__ W2,
                                                  const float* __restrict__ W4, int N) {
    int t = threadIdx.x;
    float4 z4 = make_float4(0.f, 0.f, 0.f, 0.f);
    int gsz = gridDim.x * 256;
    for (int i = blockIdx.x * 256 + t; i < N * 16; i += gsz) {
        ((float4*)g_agg)[i] = z4;
        if (i < N) ((float4*)g_Sx)[i] = z4;
    }

    __shared__ float sW3t[64 * 64];   // [k][o]
    __shared__ float smu[64 * 64];    // [n_local][k]
    for (int i = t; i < 64 * 64; i += 256) {
        int o = i >> 6, k = i & 63;
        sW3t[k * 64 + o] = W3[i];
    }
    int base = blockIdx.x * 64;
    for (int i = t; i < 64 * 16; i += 256) {
        int nl = i >> 4, q = i & 15;
        int n = base + nl;
        float4 m = (n < N) ? ((const float4*)mu)[(size_t)n * 16 + q] : z4;
        ((float4*)smu)[nl * 16 + q] = m;
    }
    __syncthreads();

    int gq = t >> 4, o4 = t & 15;     // 4-node group, 4-output group
    float4 a0 = z4, a1 = z4, a2 = z4, a3 = z4;
    const float4* w4p = (const float4*)sW3t;
    const float* m0p = smu + (gq * 4 + 0) * 64;
    const float* m1p = smu + (gq * 4 + 1) * 64;
    const float* m2p = smu + (gq * 4 + 2) * 64;
    const float* m3p = smu + (gq * 4 + 3) * 64;
#pragma unroll 8
    for (int k = 0; k < 64; k++) {
        float4 w = w4p[k * 16 + o4];
        float m0 = m0p[k], m1 = m1p[k], m2 = m2p[k], m3 = m3p[k];
        a0.x = fmaf(m0, w.x, a0.x); a0.y = fmaf(m0, w.y, a0.y);
        a0.z = fmaf(m0, w.z, a0.z); a0.w = fmaf(m0, w.w, a0.w);
        a1.x = fmaf(m1, w.x, a1.x); a1.y = fmaf(m1, w.y, a1.y);
        a1.z = fmaf(m1, w.z, a1.z); a1.w = fmaf(m1, w.w, a1.w);
        a2.x = fmaf(m2, w.x, a2.x); a2.y = fmaf(m2, w.y, a2.y);
        a2.z = fmaf(m2, w.z, a2.z); a2.w = fmaf(m2, w.w, a2.w);
        a3.x = fmaf(m3, w.x, a3.x); a3.y = fmaf(m3, w.y, a3.y);
        a3.z = fmaf(m3, w.z, a3.z); a3.w = fmaf(m3, w.w, a3.w);
    }
    float4 accs[4] = {a0, a1, a2, a3};
#pragma unroll
    for (int r = 0; r < 4; r++) {
        int n = base + gq * 4 + r;
        if (n < N) {
            float4 a = accs[r];
            float4 rr = make_float4(relu(a.x), relu(a.y), relu(a.z), relu(a.w));
            ((float4*)g_hmu)[(size_t)n * 16 + o4] = rr;
        }
    }

    // vprep: the three rank-1 vectors (block 0, threads 0..63)
    if (blockIdx.x == 0 && t < 64) {
        int o = t;
        float a = 0.f, b = 0.f, c = 0.f;
#pragma unroll 8
        for (int k = 0; k < 64; k++) {
            float w4a = W4[o * 192 + k];
            float w4b = W4[o * 192 + 64 + k];
            float w1 = W1[k], w2 = W2[k];
            a = fmaf(w4a, relu(w1), a);
            b = fmaf(w4a, relu(-w1), b);
            c = fmaf(w4b, relu(w2), c);
        }
        g_v[o] = a;
        g_v[64 + o] = b;
        g_v[128 + o] = c;
    }
}

// K2: scatter edge kernel. 16 threads per group; each group processes 4 edges
// (MLP=4 on the gathers), then fires red.global.add.v4 into agg[src].
__global__ __launch_bounds__(256) void k_edge(const int* __restrict__ ei,
                                              const float* __restrict__ x,
                                              const float* __restrict__ ew, int E) {
    int gid = (blockIdx.x * 256 + threadIdx.x) >> 4;
    int j = threadIdx.x & 15;
    int e0 = gid * 4;
    if (e0 >= E) return;
    int ne = min(4, E - e0);

    int srcs[4], dsts[4];
#pragma unroll
    for (int q = 0; q < 4; q++) {
        if (q < ne) {
            srcs[q] = ei[e0 + q];
            dsts[q] = ei[(size_t)E + e0 + q];
        }
    }
    const float4* hmu4 = (const float4*)g_hmu;
    float4 v[4];
#pragma unroll
    for (int q = 0; q < 4; q++)
        if (q < ne) v[q] = hmu4[(size_t)dsts[q] * 16 + j];
#pragma unroll
    for (int q = 0; q < 4; q++)
        if (q < ne) red_add_v4(&g_agg[(size_t)srcs[q] * 64 + (size_t)j * 4], v[q]);

    if (j == 0) {
#pragma unroll
        for (int q = 0; q < 4; q++) {
            if (q < ne) {
                float xd = x[dsts[q]];
                red_add_v4(&g_Sx[(size_t)srcs[q] * 4],
                           make_float4(relu(xd), relu(-xd), ew[e0 + q], 0.f));
            }
        }
    }
}

// K3: finalize. 64 nodes/block, 4x4 register tile. agg -> smem -> GEMV vs W4c
//     + rank-1 scalar terms + epilogue relu chain.
__global__ __launch_bounds__(256) void k_final(const float* __restrict__ x,
                                               const float* __restrict__ W1,
                                               const float* __restrict__ W4,
                                               float* __restrict__ out, int N) {
    __shared__ float sW4t[64 * 64];   // [k][o] of W4 cols 128..191
    __shared__ float sAgg[64 * 64];   // [n_local][k]
    __shared__ float sv[192];
    __shared__ float sW1[64];
    int t = threadIdx.x;
    float4 z4 = make_float4(0.f, 0.f, 0.f, 0.f);
    for (int i = t; i < 64 * 64; i += 256) {
        int o = i >> 6, k = i & 63;
        sW4t[k * 64 + o] = W4[o * 192 + 128 + k];
    }
    if (t < 192) sv[t] = g_v[t];
    if (t < 64)  sW1[t] = W1[t];
    int base = blockIdx.x * 64;
    for (int i = t; i < 64 * 16; i += 256) {
        int nl = i >> 4, q = i & 15;
        int n = base + nl;
        float4 a = (n < N) ? ((const float4*)g_agg)[(size_t)n * 16 + q] : z4;
        ((float4*)sAgg)[nl * 16 + q] = a;
    }
    __syncthreads();

    int gq = t >> 4, o4 = t & 15;
    int o0 = o4 * 4;
    float4 a0 = z4, a1 = z4, a2 = z4, a3 = z4;
    const float4* w4p = (const float4*)sW4t;
    const float* m0p = sAgg + (gq * 4 + 0) * 64;
    const float* m1p = sAgg + (gq * 4 + 1) * 64;
    const float* m2p = sAgg + (gq * 4 + 2) * 64;
    const float* m3p = sAgg + (gq * 4 + 3) * 64;
#pragma unroll 8
    for (int k = 0; k < 64; k++) {
        float4 w = w4p[k * 16 + o4];
        float m0 = m0p[k], m1 = m1p[k], m2 = m2p[k], m3 = m3p[k];
        a0.x = fmaf(m0, w.x, a0.x); a0.y = fmaf(m0, w.y, a0.y);
        a0.z = fmaf(m0, w.z, a0.z); a0.w = fmaf(m0, w.w, a0.w);
        a1.x = fmaf(m1, w.x, a1.x); a1.y = fmaf(m1, w.y, a1.y);
        a1.z = fmaf(m1, w.z, a1.z); a1.w = fmaf(m1, w.w, a1.w);
        a2.x = fmaf(m2, w.x, a2.x); a2.y = fmaf(m2, w.y, a2.y);
        a2.z = fmaf(m2, w.z, a2.z); a2.w = fmaf(m2, w.w, a2.w);
        a3.x = fmaf(m3, w.x, a3.x); a3.y = fmaf(m3, w.y, a3.y);
        a3.z = fmaf(m3, w.z, a3.z); a3.w = fmaf(m3, w.w, a3.w);
    }
    float4 zt[4] = {a0, a1, a2, a3};
    float4 v1  = make_float4(sv[o0], sv[o0 + 1], sv[o0 + 2], sv[o0 + 3]);
    float4 v1n = make_float4(sv[64 + o0], sv[64 + o0 + 1], sv[64 + o0 + 2], sv[64 + o0 + 3]);
    float4 v2  = make_float4(sv[128 + o0], sv[128 + o0 + 1], sv[128 + o0 + 2], sv[128 + o0 + 3]);
    float4 w1v = make_float4(sW1[o0], sW1[o0 + 1], sW1[o0 + 2], sW1[o0 + 3]);
#pragma unroll
    for (int r = 0; r < 4; r++) {
        int n = base + gq * 4 + r;
        if (n >= N) break;
        float4 sx = ((const float4*)g_Sx)[n];
        float4 z = zt[r];
        z.x += sx.x * v1.x + sx.y * v1n.x + sx.z * v2.x;
        z.y += sx.x * v1.y + sx.y * v1n.y + sx.z * v2.y;
        z.z += sx.x * v1.z + sx.y * v1n.z + sx.z * v2.z;
        z.w += sx.x * v1.w + sx.y * v1n.w + sx.z * v2.w;
        float xn = x[n];
        float4 hm = ((const float4*)g_hmu)[(size_t)n * 16 + o4];
        float4 rr;
        rr.x = relu(relu(xn * w1v.x) + hm.x + relu(z.x));
        rr.y = relu(relu(xn * w1v.y) + hm.y + relu(z.y));
        rr.z = relu(relu(xn * w1v.z) + hm.z + relu(z.z));
        rr.w = relu(relu(xn * w1v.w) + hm.w + relu(z.w));
        ((float4*)out)[(size_t)n * 16 + o4] = rr;
    }
}

extern "C" void kernel_launch(void* const* d_in, const int* in_sizes, int n_in,
                              void* d_out, int out_size) {
    const float* mu  = (const float*)d_in[0];
    const float* x   = (const float*)d_in[1];
    const int*   ei  = (const int*)d_in[2];     // int32 (JAX x64 disabled)
    const float* ew  = (const float*)d_in[3];
    const float* W1  = (const float*)d_in[4];
    const float* W2  = (const float*)d_in[5];
    const float* W3  = (const float*)d_in[6];
    const float* W4  = (const float*)d_in[7];
    float* out = (float*)d_out;

    int N = in_sizes[1];   // x: [N,1]
    int E = in_sizes[3];   // edge_w: [E]

    k_hmu_zero<<<(N + 63) / 64, 256>>>(mu, W3, W1, W2, W4, N);

    int ngroups = (E + 3) / 4;                       // 4 edges per 16-thread group
    int blocks = (ngroups * 16 + 255) / 256;
    k_edge<<<blocks, 256>>>(ei, x, ew, E);

    k_final<<<(N + 63) / 64, 256>>>(x, W1, W4, out, N);
}

// round 9
// speedup vs baseline: 1.9541x; 1.0736x over previous
#include <cuda_runtime.h>
#include <cstdint>

#define MAXN 50000
#define MAXE 1600000
#define D 64

// ---- scratch (__device__ globals; no allocations allowed) ----
__device__ float g_agg[MAXN * D];    // segment-sum of h_mu[dst] over src
__device__ float g_Sx[MAXN * 4];     // per-src scalar sums: Spos, Sneg, Sw, pad
__device__ float g_hmu[MAXN * D];    // relu(mu @ W3^T)
__device__ float g_v[3 * D];         // v1=W4a@relu(W1), v1n=W4a@relu(-W1), v2=W4b@relu(W2)

__device__ __forceinline__ float relu(float a) { return fmaxf(a, 0.f); }

__device__ __forceinline__ void red_add_v4(float* addr, float4 v) {
    asm volatile("red.global.add.v4.f32 [%0], {%1,%2,%3,%4};"
                 :: "l"(addr), "f"(v.x), "f"(v.y), "f"(v.z), "f"(v.w)
                 : "memory");
}

// 4-node x 4-output register-tile GEMM inner loop over smem.
// sM: [64 nodes][64 k], sW: [64 k][64 o] (as float4 columns).
// Node operands fetched as float4 per 4 k-steps: 8 LDS.128 per 64 FMA.
__device__ __forceinline__ void gemm_tile_4x4(const float* sM, const float* sW,
                                              int gq, int o4, float4 acc[4]) {
    const float4* m0 = (const float4*)(sM + (gq * 4 + 0) * 64);
    const float4* m1 = (const float4*)(sM + (gq * 4 + 1) * 64);
    const float4* m2 = (const float4*)(sM + (gq * 4 + 2) * 64);
    const float4* m3 = (const float4*)(sM + (gq * 4 + 3) * 64);
    const float4* w4 = (const float4*)sW;
#pragma unroll
    for (int k4 = 0; k4 < 16; k4++) {
        float4 q0 = m0[k4], q1 = m1[k4], q2 = m2[k4], q3 = m3[k4];
        const float* f0 = &q0.x;
        const float* f1 = &q1.x;
        const float* f2 = &q2.x;
        const float* f3 = &q3.x;
#pragma unroll
        for (int r = 0; r < 4; r++) {
            float4 w = w4[(k4 * 4 + r) * 16 + o4];
            float s0 = f0[r], s1 = f1[r], s2 = f2[r], s3 = f3[r];
            acc[0].x = fmaf(s0, w.x, acc[0].x); acc[0].y = fmaf(s0, w.y, acc[0].y);
            acc[0].z = fmaf(s0, w.z, acc[0].z); acc[0].w = fmaf(s0, w.w, acc[0].w);
            acc[1].x = fmaf(s1, w.x, acc[1].x); acc[1].y = fmaf(s1, w.y, acc[1].y);
            acc[1].z = fmaf(s1, w.z, acc[1].z); acc[1].w = fmaf(s1, w.w, acc[1].w);
            acc[2].x = fmaf(s2, w.x, acc[2].x); acc[2].y = fmaf(s2, w.y, acc[2].y);
            acc[2].z = fmaf(s2, w.z, acc[2].z); acc[2].w = fmaf(s2, w.w, acc[2].w);
            acc[3].x = fmaf(s3, w.x, acc[3].x); acc[3].y = fmaf(s3, w.y, acc[3].y);
            acc[3].z = fmaf(s3, w.z, acc[3].z); acc[3].w = fmaf(s3, w.w, acc[3].w);
        }
    }
}

// K1: h_mu = relu(mu @ W3^T). 64 nodes/block, 4x4 register tile.
//     Prologue zeroes g_agg/g_Sx; block 0 computes the rank-1 vectors.
__global__ __launch_bounds__(256) void k_hmu_zero(const float* __restrict__ mu,
                                                  const float* __restrict__ W3,
                                                  const float* __restrict__ W1,
                                                  const float* __restrict__ W2,
                                                  const float* __restrict__ W4, int N) {
    int t = threadIdx.x;
    float4 z4 = make_float4(0.f, 0.f, 0.f, 0.f);
    int gsz = gridDim.x * 256;
    for (int i = blockIdx.x * 256 + t; i < N * 16; i += gsz) {
        ((float4*)g_agg)[i] = z4;
        if (i < N) ((float4*)g_Sx)[i] = z4;
    }

    __shared__ float sW3t[64 * 64];   // [k][o]
    __shared__ float smu[64 * 64];    // [n_local][k]
    for (int i = t; i < 64 * 64; i += 256) {
        int o = i >> 6, k = i & 63;
        sW3t[k * 64 + o] = W3[i];
    }
    int base = blockIdx.x * 64;
    for (int i = t; i < 64 * 16; i += 256) {
        int nl = i >> 4, q = i & 15;
        int n = base + nl;
        float4 m = (n < N) ? ((const float4*)mu)[(size_t)n * 16 + q] : z4;
        ((float4*)smu)[nl * 16 + q] = m;
    }
    __syncthreads();

    int gq = t >> 4, o4 = t & 15;
    float4 acc[4] = {z4, z4, z4, z4};
    gemm_tile_4x4(smu, sW3t, gq, o4, acc);
#pragma unroll
    for (int r = 0; r < 4; r++) {
        int n = base + gq * 4 + r;
        if (n < N) {
            float4 a = acc[r];
            float4 rr = make_float4(relu(a.x), relu(a.y), relu(a.z), relu(a.w));
            ((float4*)g_hmu)[(size_t)n * 16 + o4] = rr;
        }
    }

    if (blockIdx.x == 0 && t < 64) {
        int o = t;
        float a = 0.f, b = 0.f, c = 0.f;
#pragma unroll 8
        for (int k = 0; k < 64; k++) {
            float w4a = W4[o * 192 + k];
            float w4b = W4[o * 192 + 64 + k];
            float w1 = W1[k], w2 = W2[k];
            a = fmaf(w4a, relu(w1), a);
            b = fmaf(w4a, relu(-w1), b);
            c = fmaf(w4b, relu(w2), c);
        }
        g_v[o] = a;
        g_v[64 + o] = b;
        g_v[128 + o] = c;
    }
}

// K2: scatter edge kernel. 16 threads per group; each group processes 8 edges
// (MLP=8 on the gathers), indices loaded as int4, then 8 fire-and-forget
// red.global.add.v4 into agg[src]. Lane 0 reduces the 3 scalars.
__global__ __launch_bounds__(256) void k_edge(const int* __restrict__ ei,
                                              const float* __restrict__ x,
                                              const float* __restrict__ ew, int E) {
    int gid = (blockIdx.x * 256 + threadIdx.x) >> 4;
    int j = threadIdx.x & 15;
    int e0 = gid * 8;
    if (e0 >= E) return;
    const float4* hmu4 = (const float4*)g_hmu;

    if (e0 + 8 <= E) {
        int4 sa = *(const int4*)(ei + e0);
        int4 sb = *(const int4*)(ei + e0 + 4);
        int4 da = *(const int4*)(ei + (size_t)E + e0);
        int4 db = *(const int4*)(ei + (size_t)E + e0 + 4);
        int srcs[8] = {sa.x, sa.y, sa.z, sa.w, sb.x, sb.y, sb.z, sb.w};
        int dsts[8] = {da.x, da.y, da.z, da.w, db.x, db.y, db.z, db.w};
        float4 v[8];
#pragma unroll
        for (int q = 0; q < 8; q++)
            v[q] = hmu4[(size_t)dsts[q] * 16 + j];
#pragma unroll
        for (int q = 0; q < 8; q++)
            red_add_v4(&g_agg[(size_t)srcs[q] * 64 + (size_t)j * 4], v[q]);
        if (j == 0) {
#pragma unroll
            for (int q = 0; q < 8; q++) {
                float xd = x[dsts[q]];
                red_add_v4(&g_Sx[(size_t)srcs[q] * 4],
                           make_float4(relu(xd), relu(-xd), ew[e0 + q], 0.f));
            }
        }
    } else {
        for (int e = e0; e < E; e++) {
            int src = ei[e];
            int dst = ei[(size_t)E + e];
            float4 v = hmu4[(size_t)dst * 16 + j];
            red_add_v4(&g_agg[(size_t)src * 64 + (size_t)j * 4], v);
            if (j == 0) {
                float xd = x[dst];
                red_add_v4(&g_Sx[(size_t)src * 4],
                           make_float4(relu(xd), relu(-xd), ew[e], 0.f));
            }
        }
    }
}

// K3: finalize. 64 nodes/block, 4x4 register tile. agg -> smem -> GEMV vs W4c
//     + rank-1 scalar terms + epilogue relu chain.
__global__ __launch_bounds__(256) void k_final(const float* __restrict__ x,
                                               const float* __restrict__ W1,
                                               const float* __restrict__ W4,
                                               float* __restrict__ out, int N) {
    __shared__ float sW4t[64 * 64];   // [k][o] of W4 cols 128..191
    __shared__ float sAgg[64 * 64];   // [n_local][k]
    __shared__ float sv[192];
    __shared__ float sW1[64];
    int t = threadIdx.x;
    float4 z4 = make_float4(0.f, 0.f, 0.f, 0.f);
    for (int i = t; i < 64 * 64; i += 256) {
        int o = i >> 6, k = i & 63;
        sW4t[k * 64 + o] = W4[o * 192 + 128 + k];
    }
    if (t < 192) sv[t] = g_v[t];
    if (t < 64)  sW1[t] = W1[t];
    int base = blockIdx.x * 64;
    for (int i = t; i < 64 * 16; i += 256) {
        int nl = i >> 4, q = i & 15;
        int n = base + nl;
        float4 a = (n < N) ? ((const float4*)g_agg)[(size_t)n * 16 + q] : z4;
        ((float4*)sAgg)[nl * 16 + q] = a;
    }
    __syncthreads();

    int gq = t >> 4, o4 = t & 15;
    int o0 = o4 * 4;
    float4 acc[4] = {z4, z4, z4, z4};
    gemm_tile_4x4(sAgg, sW4t, gq, o4, acc);

    float4 v1  = make_float4(sv[o0], sv[o0 + 1], sv[o0 + 2], sv[o0 + 3]);
    float4 v1n = make_float4(sv[64 + o0], sv[64 + o0 + 1], sv[64 + o0 + 2], sv[64 + o0 + 3]);
    float4 v2  = make_float4(sv[128 + o0], sv[128 + o0 + 1], sv[128 + o0 + 2], sv[128 + o0 + 3]);
    float4 w1v = make_float4(sW1[o0], sW1[o0 + 1], sW1[o0 + 2], sW1[o0 + 3]);
#pragma unroll
    for (int r = 0; r < 4; r++) {
        int n = base + gq * 4 + r;
        if (n >= N) break;
        float4 sx = ((const float4*)g_Sx)[n];
        float4 z = acc[r];
        z.x += sx.x * v1.x + sx.y * v1n.x + sx.z * v2.x;
        z.y += sx.x * v1.y + sx.y * v1n.y + sx.z * v2.y;
        z.z += sx.x * v1.z + sx.y * v1n.z + sx.z * v2.z;
        z.w += sx.x * v1.w + sx.y * v1n.w + sx.z * v2.w;
        float xn = x[n];
        float4 hm = ((const float4*)g_hmu)[(size_t)n * 16 + o4];
        float4 rr;
        rr.x = relu(relu(xn * w1v.x) + hm.x + relu(z.x));
        rr.y = relu(relu(xn * w1v.y) + hm.y + relu(z.y));
        rr.z = relu(relu(xn * w1v.z) + hm.z + relu(z.z));
        rr.w = relu(relu(xn * w1v.w) + hm.w + relu(z.w));
        ((float4*)out)[(size_t)n * 16 + o4] = rr;
    }
}

extern "C" void kernel_launch(void* const* d_in, const int* in_sizes, int n_in,
                              void* d_out, int out_size) {
    const float* mu  = (const float*)d_in[0];
    const float* x   = (const float*)d_in[1];
    const int*   ei  = (const int*)d_in[2];     // int32 (JAX x64 disabled)
    const float* ew  = (const float*)d_in[3];
    const float* W1  = (const float*)d_in[4];
    const float* W2  = (const float*)d_in[5];
    const float* W3  = (const float*)d_in[6];
    const float* W4  = (const float*)d_in[7];
    float* out = (float*)d_out;

    int N = in_sizes[1];   // x: [N,1]
    int E = in_sizes[3];   // edge_w: [E]

    k_hmu_zero<<<(N + 63) / 64, 256>>>(mu, W3, W1, W2, W4, N);

    int ngroups = (E + 7) / 8;                       // 8 edges per 16-thread group
    int blocks = (ngroups * 16 + 255) / 256;
    k_edge<<<blocks, 256>>>(ei, x, ew, E);

    k_final<<<(N + 63) / 64, 256>>>(x, W1, W4, out, N);
}